// round 2
// baseline (speedup 1.0000x reference)
#include <cuda_runtime.h>
#include <cuda_bf16.h>
#include <stdint.h>
#include <stddef.h>

#define DIM   1024
#define BQ    2048
#define CC    65536
#define KSEL  8
#define KCAND 32

#define BM 128
#define BN 128
#define BK 32
#define LDS_A 40              // BK + 8 bf16 pad -> 80B row stride, conflict-free ldmatrix
#define NT (DIM / BK)         // 32 k-iterations

// ---------------- scratch (device globals; no allocations allowed) ----------------
static __device__ __nv_bfloat16 g_Qb[(size_t)BQ * DIM];      // 4 MB
static __device__ __nv_bfloat16 g_Kb[(size_t)CC * DIM];      // 128 MB
static __device__ float         g_rnorm[CC];                 // 256 KB
static __device__ __nv_bfloat16 g_S[(size_t)BQ * CC];        // 256 MB (bf16 sims)
static __device__ int           g_cand[BQ * KCAND];          // 256 KB

// ---------------- small helpers ----------------
__device__ __forceinline__ void cp_async16(void* smem, const void* gmem) {
    uint32_t s = (uint32_t)__cvta_generic_to_shared(smem);
    asm volatile("cp.async.cg.shared.global [%0], [%1], 16;\n" :: "r"(s), "l"(gmem) : "memory");
}

__device__ __forceinline__ void mma16816(float* d, const uint32_t* a, const uint32_t* b) {
    asm volatile(
        "mma.sync.aligned.m16n8k16.row.col.f32.bf16.bf16.f32 "
        "{%0,%1,%2,%3}, {%4,%5,%6,%7}, {%8,%9}, {%0,%1,%2,%3};\n"
        : "+f"(d[0]), "+f"(d[1]), "+f"(d[2]), "+f"(d[3])
        : "r"(a[0]), "r"(a[1]), "r"(a[2]), "r"(a[3]), "r"(b[0]), "r"(b[1]));
}

// ---------------- prep: query -> bf16 ----------------
__global__ void prep_q_kernel(const float4* __restrict__ q) {
    int i = blockIdx.x * blockDim.x + threadIdx.x;   // over BQ*DIM/4
    float4 v = q[i];
    union { __nv_bfloat162 h2[2]; uint2 u; } cv;
    cv.h2[0] = __floats2bfloat162_rn(v.x, v.y);
    cv.h2[1] = __floats2bfloat162_rn(v.z, v.w);
    ((uint2*)g_Qb)[i] = cv.u;
}

// ---------------- prep: keys -> bf16 + inverse norms ----------------
__global__ void prep_keys_kernel(const float* __restrict__ keys) {
    int row = blockIdx.x;
    int t = threadIdx.x, lane = t & 31, w = t >> 5;
    const float4* kr = (const float4*)(keys + (size_t)row * DIM);   // 256 float4 per row
    float4 v = kr[t];
    union { __nv_bfloat162 h2[2]; uint2 u; } cv;
    cv.h2[0] = __floats2bfloat162_rn(v.x, v.y);
    cv.h2[1] = __floats2bfloat162_rn(v.z, v.w);
    ((uint2*)(g_Kb + (size_t)row * DIM))[t] = cv.u;
    float ss = v.x*v.x + v.y*v.y + v.z*v.z + v.w*v.w;
    #pragma unroll
    for (int o = 16; o; o >>= 1) ss += __shfl_xor_sync(0xFFFFFFFFu, ss, o);
    __shared__ float sred[8];
    if (lane == 0) sred[w] = ss;
    __syncthreads();
    if (t == 0) {
        float tot = 0.f;
        #pragma unroll
        for (int j = 0; j < 8; j++) tot += sred[j];
        g_rnorm[row] = 1.0f / fmaxf(sqrtf(tot), 1e-12f);
    }
}

// ---------------- GEMM: S[b,c] = bf16( (Qb . Kb_c) * rnorm[c] ) ----------------
__global__ __launch_bounds__(256, 2) void gemm_kernel() {
    __shared__ __nv_bfloat16 sA[2][BM * LDS_A];
    __shared__ __nv_bfloat16 sB[2][BN * LDS_A];
    __shared__ float sRn[BN];

    const int tid = threadIdx.x;
    const int m0 = blockIdx.y * BM;
    const int n0 = blockIdx.x * BN;

    if (tid < BN) sRn[tid] = g_rnorm[n0 + tid];

    const int warp = tid >> 5, lane = tid & 31;
    const int wm = (warp & 1) * 64;
    const int wn = (warp >> 1) * 32;

    float acc[4][4][4];
    #pragma unroll
    for (int i = 0; i < 4; i++)
        #pragma unroll
        for (int j = 0; j < 4; j++)
            #pragma unroll
            for (int r = 0; r < 4; r++) acc[i][j][r] = 0.f;

#define LOAD_STAGE(buf, kt) do {                                                          \
        int k0_ = (kt) * BK;                                                              \
        for (int h = 0; h < 2; h++) {                                                     \
            int c_ = tid + h * 256;                                                       \
            int row_ = c_ >> 2, seg_ = c_ & 3;                                            \
            cp_async16(&sA[buf][row_ * LDS_A + seg_ * 8],                                 \
                       g_Qb + (size_t)(m0 + row_) * DIM + k0_ + seg_ * 8);                \
            cp_async16(&sB[buf][row_ * LDS_A + seg_ * 8],                                 \
                       g_Kb + (size_t)(n0 + row_) * DIM + k0_ + seg_ * 8);                \
        }                                                                                 \
        asm volatile("cp.async.commit_group;\n" ::: "memory");                            \
    } while (0)

    LOAD_STAGE(0, 0);

    for (int kt = 0; kt < NT; kt++) {
        if (kt + 1 < NT) {
            LOAD_STAGE((kt + 1) & 1, kt + 1);
            asm volatile("cp.async.wait_group 1;\n" ::: "memory");
        } else {
            asm volatile("cp.async.wait_group 0;\n" ::: "memory");
        }
        __syncthreads();

        const int buf = kt & 1;
        #pragma unroll
        for (int ks = 0; ks < 2; ks++) {
            const int k0 = ks * 16;
            uint32_t a[4][4], bfr[4][2];
            #pragma unroll
            for (int mt = 0; mt < 4; mt++) {
                const __nv_bfloat16* p =
                    &sA[buf][(wm + mt * 16 + (lane & 15)) * LDS_A + k0 + (lane >> 4) * 8];
                uint32_t ad = (uint32_t)__cvta_generic_to_shared(p);
                asm volatile("ldmatrix.sync.aligned.m8n8.x4.shared.b16 {%0,%1,%2,%3}, [%4];\n"
                             : "=r"(a[mt][0]), "=r"(a[mt][1]), "=r"(a[mt][2]), "=r"(a[mt][3])
                             : "r"(ad));
            }
            #pragma unroll
            for (int np = 0; np < 2; np++) {
                const __nv_bfloat16* p =
                    &sB[buf][(wn + np * 16 + (lane & 7) + ((lane >> 4) << 3)) * LDS_A +
                             k0 + ((lane >> 3) & 1) * 8];
                uint32_t ad = (uint32_t)__cvta_generic_to_shared(p);
                uint32_t r0, r1, r2, r3;
                asm volatile("ldmatrix.sync.aligned.m8n8.x4.shared.b16 {%0,%1,%2,%3}, [%4];\n"
                             : "=r"(r0), "=r"(r1), "=r"(r2), "=r"(r3) : "r"(ad));
                bfr[np * 2][0] = r0; bfr[np * 2][1] = r1;
                bfr[np * 2 + 1][0] = r2; bfr[np * 2 + 1][1] = r3;
            }
            #pragma unroll
            for (int mt = 0; mt < 4; mt++)
                #pragma unroll
                for (int nt = 0; nt < 4; nt++)
                    mma16816(acc[mt][nt], a[mt], bfr[nt]);
        }
        __syncthreads();
    }
#undef LOAD_STAGE

    // epilogue: scale by rnorm, store bf16 sims
    #pragma unroll
    for (int mt = 0; mt < 4; mt++) {
        #pragma unroll
        for (int nt = 0; nt < 4; nt++) {
            int r0 = m0 + wm + mt * 16 + (lane >> 2);
            int cl = wn + nt * 8 + (lane & 3) * 2;
            float rnA = sRn[cl], rnB = sRn[cl + 1];
            size_t base = (size_t)r0 * CC + n0 + cl;
            *(__nv_bfloat162*)&g_S[base] =
                __floats2bfloat162_rn(acc[mt][nt][0] * rnA, acc[mt][nt][1] * rnB);
            *(__nv_bfloat162*)&g_S[base + (size_t)8 * CC] =
                __floats2bfloat162_rn(acc[mt][nt][2] * rnA, acc[mt][nt][3] * rnB);
        }
    }
}

// ---------------- candidate selection: per query, top-32 of the bf16 sims ----------------
__global__ void select_kernel() {
    const int q = blockIdx.x;
    const int t = threadIdx.x;
    const __nv_bfloat16* row = g_S + (size_t)q * CC;

    // per-thread top-8 over a strided 256-element chunk (coalesced)
    float v[8]; int id[8];
    #pragma unroll
    for (int j = 0; j < 8; j++) { v[j] = -3e38f; id[j] = -1; }
    for (int i = 0; i < CC / 256; i++) {
        int idx = t + (i << 8);
        float val = __bfloat162float(row[idx]);
        if (val > v[7]) {
            v[7] = val; id[7] = idx;
            #pragma unroll
            for (int j = 7; j > 0; j--)
                if (v[j] > v[j - 1]) {
                    float tv = v[j]; v[j] = v[j - 1]; v[j - 1] = tv;
                    int ti = id[j]; id[j] = id[j - 1]; id[j - 1] = ti;
                }
        }
    }

    __shared__ float sv[256 * 8];
    __shared__ int   si[256 * 8];
    __shared__ float wbv[8];
    __shared__ int   wbs[8];
    #pragma unroll
    for (int j = 0; j < 8; j++) { sv[(t << 3) + j] = v[j]; si[(t << 3) + j] = id[j]; }
    __syncthreads();

    // 32 extraction rounds (deterministic; slot-index tiebreak)
    for (int r = 0; r < KCAND; r++) {
        float bv = -3e38f; int bs = 0;
        #pragma unroll
        for (int j = 0; j < 8; j++) {
            float x = sv[(t << 3) + j];
            if (x > bv) { bv = x; bs = (t << 3) + j; }
        }
        #pragma unroll
        for (int o = 16; o; o >>= 1) {
            float ov = __shfl_xor_sync(0xFFFFFFFFu, bv, o);
            int   os = __shfl_xor_sync(0xFFFFFFFFu, bs, o);
            if (ov > bv || (ov == bv && os < bs)) { bv = ov; bs = os; }
        }
        if ((t & 31) == 0) { wbv[t >> 5] = bv; wbs[t >> 5] = bs; }
        __syncthreads();
        if (t == 0) {
            float gb = wbv[0]; int gs = wbs[0];
            #pragma unroll
            for (int w = 1; w < 8; w++)
                if (wbv[w] > gb || (wbv[w] == gb && wbs[w] < gs)) { gb = wbv[w]; gs = wbs[w]; }
            g_cand[q * KCAND + r] = si[gs];
            sv[gs] = -3e38f;
        }
        __syncthreads();
    }
}

// ---------------- usage init: out_usage = memory_usage ----------------
__global__ void usage_init_kernel(const float* __restrict__ u, float* __restrict__ out_u) {
    int i = blockIdx.x * blockDim.x + threadIdx.x;
    out_u[i] = u[i];
}

// ---------------- exact fp32 rescore of 32 candidates + top-8 + gather + counts ----------------
__global__ void rescore_gather_kernel(const float* __restrict__ q,
                                      const float* __restrict__ keys,
                                      const float* __restrict__ vals,
                                      float* __restrict__ out_k,
                                      float* __restrict__ out_v,
                                      float* __restrict__ out_u) {
    const int b = blockIdx.x;
    const int t = threadIdx.x, lane = t & 31, w = t >> 5;
    __shared__ float qs[DIM];
    __shared__ float simv[KCAND];
    __shared__ int   simi[KCAND];
    __shared__ int   topi[KSEL];

    ((float4*)qs)[t] = ((const float4*)(q + (size_t)b * DIM))[t];
    __syncthreads();

    #pragma unroll
    for (int jj = 0; jj < 4; jj++) {
        int j = w * 4 + jj;
        int c = g_cand[b * KCAND + j];
        const float* kr = keys + (size_t)c * DIM;
        float s = 0.f;
        #pragma unroll 8
        for (int i = lane; i < DIM; i += 32) s = fmaf(qs[i], kr[i], s);
        #pragma unroll
        for (int o = 16; o; o >>= 1) s += __shfl_xor_sync(0xFFFFFFFFu, s, o);
        if (lane == 0) { simv[j] = s * g_rnorm[c]; simi[j] = c; }
    }
    __syncthreads();

    if (t == 0) {
        unsigned used = 0;
        for (int r = 0; r < KSEL; r++) {
            int best = -1;
            for (int j = 0; j < KCAND; j++) {
                if (used & (1u << j)) continue;
                if (best < 0 || simv[j] > simv[best] ||
                    (simv[j] == simv[best] && simi[j] < simi[best])) best = j;
            }
            used |= 1u << best;
            topi[r] = simi[best];
        }
    }
    __syncthreads();

    for (int r = 0; r < KSEL; r++) {
        int c = topi[r];
        const float4* sk = (const float4*)(keys + (size_t)c * DIM);
        const float4* sw = (const float4*)(vals + (size_t)c * DIM);
        float4* dk = (float4*)(out_k + ((size_t)b * KSEL + r) * DIM);
        float4* dv = (float4*)(out_v + ((size_t)b * KSEL + r) * DIM);
        dk[t] = sk[t];
        dv[t] = sw[t];
    }
    if (t < KSEL) atomicAdd(&out_u[topi[t]], 1.0f);
}

// ---------------- launch ----------------
extern "C" void kernel_launch(void* const* d_in, const int* in_sizes, int n_in,
                              void* d_out, int out_size) {
    const float* query  = (const float*)d_in[0];
    const float* keys   = (const float*)d_in[1];
    const float* values = (const float*)d_in[2];
    const float* usage  = (const float*)d_in[3];
    // d_in[4] = k (fixed to 8 by problem shape / out_size)

    float* out       = (float*)d_out;
    float* out_keys  = out;
    float* out_vals  = out + (size_t)BQ * KSEL * DIM;
    float* out_usage = out + (size_t)2 * BQ * KSEL * DIM;

    prep_q_kernel<<<(BQ * DIM / 4) / 256, 256>>>((const float4*)query);
    prep_keys_kernel<<<CC, 256>>>(keys);

    dim3 ggrid(CC / BN, BQ / BM);
    gemm_kernel<<<ggrid, 256>>>();

    select_kernel<<<BQ, 256>>>();
    usage_init_kernel<<<CC / 256, 256>>>(usage, out_usage);
    rescore_gather_kernel<<<BQ, 256>>>(query, keys, values, out_keys, out_vals, out_usage);
}

// round 5
// speedup vs baseline: 1.0726x; 1.0726x over previous
#include <cuda_runtime.h>
#include <cuda_bf16.h>
#include <cuda_fp8.h>
#include <stdint.h>
#include <stddef.h>

#define DIM   1024
#define BQ    2048
#define CC    65536
#define KSEL  8
#define KCAND 32

// ---------------- fp8 GEMM geometry ----------------
#define BM 128
#define BN 128
#define BKB 64                  // 64 fp8 bytes of K per chunk
#define NCHUNK (DIM / BKB)      // 16
#define LDSB 80                 // smem row stride in bytes (64 + 16 pad -> conflict-free ldmatrix)
#define STAGE_BYTES (2 * BM * LDSB)   // A + B : 20480 B
#define STAGES 3
#define SMEM_DYN (STAGES * STAGE_BYTES)   // 61440

// ---------------- scratch (device globals; no allocations allowed) ----------------
static __device__ uint8_t       g_Qf8[(size_t)BQ * DIM];     // 2 MB   (raw query, e4m3)
static __device__ uint8_t       g_Kf8[(size_t)CC * DIM];     // 64 MB  (16*normalized keys, e4m3)
static __device__ float         g_rnorm[CC];                 // 256 KB
static __device__ __nv_bfloat16 g_S[(size_t)BQ * CC];        // 256 MB (bf16 sims, scaled)
static __device__ int           g_cand[BQ * KCAND];          // 256 KB

// ---------------- helpers ----------------
__device__ __forceinline__ void cp_async16(void* smem, const void* gmem) {
    uint32_t s = (uint32_t)__cvta_generic_to_shared(smem);
    asm volatile("cp.async.cg.shared.global [%0], [%1], 16;\n" :: "r"(s), "l"(gmem) : "memory");
}
#define CP_COMMIT() asm volatile("cp.async.commit_group;\n" ::: "memory")

// pack 4 floats -> 4 e4m3 bytes (byte i = x[i])
__device__ __forceinline__ uint32_t pack_e4m3x4(float x0, float x1, float x2, float x3) {
    uint16_t lo, hi;
    asm("cvt.rn.satfinite.e4m3x2.f32 %0, %1, %2;" : "=h"(lo) : "f"(x1), "f"(x0));
    asm("cvt.rn.satfinite.e4m3x2.f32 %0, %1, %2;" : "=h"(hi) : "f"(x3), "f"(x2));
    return (uint32_t)lo | ((uint32_t)hi << 16);
}

__device__ __forceinline__ void mma_e4m3(float* d, const uint32_t* a, const uint32_t* b) {
    asm volatile(
        "mma.sync.aligned.m16n8k32.row.col.f32.e4m3.e4m3.f32 "
        "{%0,%1,%2,%3}, {%4,%5,%6,%7}, {%8,%9}, {%0,%1,%2,%3};\n"
        : "+f"(d[0]), "+f"(d[1]), "+f"(d[2]), "+f"(d[3])
        : "r"(a[0]), "r"(a[1]), "r"(a[2]), "r"(a[3]), "r"(b[0]), "r"(b[1]));
}

// ---------------- prep: query -> e4m3 ----------------
__global__ void prep_q_kernel(const float4* __restrict__ q) {
    int i = blockIdx.x * blockDim.x + threadIdx.x;   // over BQ*DIM/4
    float4 v = q[i];
    ((uint32_t*)g_Qf8)[i] = pack_e4m3x4(v.x, v.y, v.z, v.w);
}

// ---------------- prep: keys -> 16 * normalized e4m3 + inverse norms ----------------
__global__ void prep_keys_kernel(const float* __restrict__ keys) {
    int row = blockIdx.x;
    int t = threadIdx.x, lane = t & 31, w = t >> 5;
    const float4* kr = (const float4*)(keys + (size_t)row * DIM);   // 256 float4 per row
    float4 v = kr[t];
    float ss = v.x*v.x + v.y*v.y + v.z*v.z + v.w*v.w;
    #pragma unroll
    for (int o = 16; o; o >>= 1) ss += __shfl_xor_sync(0xFFFFFFFFu, ss, o);
    __shared__ float sred[8];
    __shared__ float srn;
    if (lane == 0) sred[w] = ss;
    __syncthreads();
    if (t == 0) {
        float tot = 0.f;
        #pragma unroll
        for (int j = 0; j < 8; j++) tot += sred[j];
        float rn = 1.0f / fmaxf(sqrtf(tot), 1e-12f);
        g_rnorm[row] = rn;
        srn = rn * 16.0f;       // scale into e4m3 sweet spot (monotone per-column factor)
    }
    __syncthreads();
    float rn = srn;
    ((uint32_t*)(g_Kf8 + (size_t)row * DIM))[t] =
        pack_e4m3x4(v.x * rn, v.y * rn, v.z * rn, v.w * rn);
}

// ---------------- fp8 GEMM: S[b,c] = bf16( Qf8[b,:] . Kf8[c,:] ) ----------------
__global__ __launch_bounds__(256, 2) void gemm_kernel() {
    extern __shared__ uint8_t smem[];

    const int tid = threadIdx.x;
    const int m0 = blockIdx.y * BM;
    const int n0 = blockIdx.x * BN;
    const int warp = tid >> 5, lane = tid & 31;
    const int wm = (warp & 1) * 64;     // 2 warps in M (64 rows each)
    const int wn = (warp >> 1) * 32;    // 4 warps in N (32 cols each)

    float acc[4][4][4];
    #pragma unroll
    for (int i = 0; i < 4; i++)
        #pragma unroll
        for (int j = 0; j < 4; j++)
            #pragma unroll
            for (int r = 0; r < 4; r++) acc[i][j][r] = 0.f;

    // stage layout: A rows [0,128) then B rows [0,128), each LDSB bytes
#define LOAD_CHUNK(st, kt) do {                                                        \
        uint8_t* base_ = smem + (st) * STAGE_BYTES;                                    \
        int kb_ = (kt) * BKB;                                                          \
        _Pragma("unroll")                                                              \
        for (int h = 0; h < 4; h++) {                                                  \
            int e_ = tid + (h << 8);          /* 0..1023 */                            \
            int row_ = e_ >> 2, seg_ = e_ & 3;                                         \
            const uint8_t* g_ = (row_ < BM)                                            \
                ? g_Qf8 + (((size_t)(m0 + row_)) << 10) + kb_ + (seg_ << 4)            \
                : g_Kf8 + (((size_t)(n0 + row_ - BM)) << 10) + kb_ + (seg_ << 4);      \
            cp_async16(base_ + row_ * LDSB + (seg_ << 4), g_);                         \
        }                                                                              \
        CP_COMMIT();                                                                   \
    } while (0)

    LOAD_CHUNK(0, 0);
    LOAD_CHUNK(1, 1);
    LOAD_CHUNK(2, 2);

    for (int kt = 0; kt < NCHUNK; kt++) {
        const int st = kt % 3;
        if (kt < NCHUNK - 2)       asm volatile("cp.async.wait_group 2;\n" ::: "memory");
        else if (kt == NCHUNK - 2) asm volatile("cp.async.wait_group 1;\n" ::: "memory");
        else                       asm volatile("cp.async.wait_group 0;\n" ::: "memory");
        __syncthreads();

        const uint8_t* sA = smem + st * STAGE_BYTES;
        const uint8_t* sB = sA + BM * LDSB;

        #pragma unroll
        for (int ks = 0; ks < 2; ks++) {            // two k32 steps per 64B chunk
            const int kb = ks * 32;
            uint32_t a[4][4], bfr[4][2];
            #pragma unroll
            for (int mt = 0; mt < 4; mt++) {
                const uint8_t* p = sA + (wm + mt * 16 + (lane & 15)) * LDSB
                                      + kb + ((lane >> 4) << 4);
                uint32_t ad = (uint32_t)__cvta_generic_to_shared(p);
                asm volatile("ldmatrix.sync.aligned.m8n8.x4.shared.b16 {%0,%1,%2,%3}, [%4];\n"
                             : "=r"(a[mt][0]), "=r"(a[mt][1]), "=r"(a[mt][2]), "=r"(a[mt][3])
                             : "r"(ad));
            }
            #pragma unroll
            for (int np = 0; np < 2; np++) {        // 16 n-rows per x4
                const uint8_t* p = sB + (wn + np * 16 + (lane & 15)) * LDSB
                                      + kb + ((lane >> 4) << 4);
                uint32_t ad = (uint32_t)__cvta_generic_to_shared(p);
                uint32_t r0, r1, r2, r3;
                asm volatile("ldmatrix.sync.aligned.m8n8.x4.shared.b16 {%0,%1,%2,%3}, [%4];\n"
                             : "=r"(r0), "=r"(r1), "=r"(r2), "=r"(r3) : "r"(ad));
                // m0: n(0-7) k0-15 | m1: n(8-15) k0-15 | m2: n(0-7) k16-31 | m3: n(8-15) k16-31
                bfr[np * 2][0]     = r0; bfr[np * 2][1]     = r2;
                bfr[np * 2 + 1][0] = r1; bfr[np * 2 + 1][1] = r3;
            }
            #pragma unroll
            for (int mt = 0; mt < 4; mt++)
                #pragma unroll
                for (int nt = 0; nt < 4; nt++)
                    mma_e4m3(acc[mt][nt], a[mt], bfr[nt]);
        }
        __syncthreads();
        if (kt + 3 < NCHUNK) LOAD_CHUNK(st, kt + 3);
    }
#undef LOAD_CHUNK

    // epilogue: store bf16 sims (keys pre-scaled; no per-column factor needed)
    #pragma unroll
    for (int mt = 0; mt < 4; mt++) {
        #pragma unroll
        for (int nt = 0; nt < 4; nt++) {
            int r0 = m0 + wm + mt * 16 + (lane >> 2);
            int cl = n0 + wn + nt * 8 + (lane & 3) * 2;
            size_t base = (size_t)r0 * CC + cl;
            *(__nv_bfloat162*)&g_S[base] =
                __floats2bfloat162_rn(acc[mt][nt][0], acc[mt][nt][1]);
            *(__nv_bfloat162*)&g_S[base + (size_t)8 * CC] =
                __floats2bfloat162_rn(acc[mt][nt][2], acc[mt][nt][3]);
        }
    }
}

// ---------------- candidate selection: per query, top-32 of the bf16 sims ----------------
__global__ void select_kernel() {
    const int q = blockIdx.x;
    const int t = threadIdx.x;
    const uint4* row = (const uint4*)(g_S + (size_t)q * CC);

    float v[8]; int id[8];
    #pragma unroll
    for (int j = 0; j < 8; j++) { v[j] = -3e38f; id[j] = -1; }

    for (int i = 0; i < CC / 2048; i++) {           // 32 iterations, 8 bf16 per iter
        union { uint4 u; __nv_bfloat162 h[4]; } d;
        d.u = row[(i << 8) + t];
        __nv_bfloat162 m01 = __hmax2(d.h[0], d.h[1]);
        __nv_bfloat162 m23 = __hmax2(d.h[2], d.h[3]);
        __nv_bfloat162 mm  = __hmax2(m01, m23);
        float mx = fmaxf(__bfloat162float(__low2bfloat16(mm)),
                         __bfloat162float(__high2bfloat16(mm)));
        if (mx > v[7]) {
            int base = ((i << 8) + t) << 3;
            float f[8];
            #pragma unroll
            for (int p = 0; p < 4; p++) {
                f[p * 2]     = __bfloat162float(__low2bfloat16(d.h[p]));
                f[p * 2 + 1] = __bfloat162float(__high2bfloat16(d.h[p]));
            }
            #pragma unroll
            for (int e = 0; e < 8; e++) {
                if (f[e] > v[7]) {
                    v[7] = f[e]; id[7] = base + e;
                    #pragma unroll
                    for (int j = 7; j > 0; j--)
                        if (v[j] > v[j - 1]) {
                            float tv = v[j]; v[j] = v[j - 1]; v[j - 1] = tv;
                            int ti = id[j]; id[j] = id[j - 1]; id[j - 1] = ti;
                        }
                }
            }
        }
    }

    __shared__ float sv[256 * 8];
    __shared__ int   si[256 * 8];
    __shared__ float wbv[8];
    __shared__ int   wbs[8];
    #pragma unroll
    for (int j = 0; j < 8; j++) { sv[(t << 3) + j] = v[j]; si[(t << 3) + j] = id[j]; }
    __syncthreads();

    for (int r = 0; r < KCAND; r++) {
        float bv = -3e38f; int bs = 0;
        #pragma unroll
        for (int j = 0; j < 8; j++) {
            float x = sv[(t << 3) + j];
            if (x > bv) { bv = x; bs = (t << 3) + j; }
        }
        #pragma unroll
        for (int o = 16; o; o >>= 1) {
            float ov = __shfl_xor_sync(0xFFFFFFFFu, bv, o);
            int   os = __shfl_xor_sync(0xFFFFFFFFu, bs, o);
            if (ov > bv || (ov == bv && os < bs)) { bv = ov; bs = os; }
        }
        if ((t & 31) == 0) { wbv[t >> 5] = bv; wbs[t >> 5] = bs; }
        __syncthreads();
        if (t == 0) {
            float gb = wbv[0]; int gs = wbs[0];
            #pragma unroll
            for (int w = 1; w < 8; w++)
                if (wbv[w] > gb || (wbv[w] == gb && wbs[w] < gs)) { gb = wbv[w]; gs = wbs[w]; }
            g_cand[q * KCAND + r] = si[gs];
            sv[gs] = -3e38f;
        }
        __syncthreads();
    }
}

// ---------------- usage init: out_usage = memory_usage ----------------
__global__ void usage_init_kernel(const float* __restrict__ u, float* __restrict__ out_u) {
    int i = blockIdx.x * blockDim.x + threadIdx.x;
    out_u[i] = u[i];
}

// ---------------- exact fp32 rescore of 32 candidates + top-8 + gather + counts ----------------
__global__ void rescore_gather_kernel(const float* __restrict__ q,
                                      const float* __restrict__ keys,
                                      const float* __restrict__ vals,
                                      float* __restrict__ out_k,
                                      float* __restrict__ out_v,
                                      float* __restrict__ out_u) {
    const int b = blockIdx.x;
    const int t = threadIdx.x, lane = t & 31, w = t >> 5;
    __shared__ float qs[DIM];
    __shared__ float simv[KCAND];
    __shared__ int   simi[KCAND];
    __shared__ int   topi[KSEL];

    ((float4*)qs)[t] = ((const float4*)(q + (size_t)b * DIM))[t];
    __syncthreads();

    #pragma unroll
    for (int jj = 0; jj < 4; jj++) {
        int j = w * 4 + jj;
        int c = g_cand[b * KCAND + j];
        const float* kr = keys + (size_t)c * DIM;
        float s = 0.f;
        #pragma unroll 8
        for (int i = lane; i < DIM; i += 32) s = fmaf(qs[i], kr[i], s);
        #pragma unroll
        for (int o = 16; o; o >>= 1) s += __shfl_xor_sync(0xFFFFFFFFu, s, o);
        if (lane == 0) { simv[j] = s * g_rnorm[c]; simi[j] = c; }
    }
    __syncthreads();

    if (t == 0) {
        unsigned used = 0;
        for (int r = 0; r < KSEL; r++) {
            int best = -1;
            for (int j = 0; j < KCAND; j++) {
                if (used & (1u << j)) continue;
                if (best < 0 || simv[j] > simv[best] ||
                    (simv[j] == simv[best] && simi[j] < simi[best])) best = j;
            }
            used |= 1u << best;
            topi[r] = simi[best];
        }
    }
    __syncthreads();

    for (int r = 0; r < KSEL; r++) {
        int c = topi[r];
        const float4* sk = (const float4*)(keys + (size_t)c * DIM);
        const float4* sw = (const float4*)(vals + (size_t)c * DIM);
        float4* dk = (float4*)(out_k + ((size_t)b * KSEL + r) * DIM);
        float4* dv = (float4*)(out_v + ((size_t)b * KSEL + r) * DIM);
        dk[t] = sk[t];
        dv[t] = sw[t];
    }
    if (t < KSEL) atomicAdd(&out_u[topi[t]], 1.0f);
}

// ---------------- launch ----------------
extern "C" void kernel_launch(void* const* d_in, const int* in_sizes, int n_in,
                              void* d_out, int out_size) {
    const float* query  = (const float*)d_in[0];
    const float* keys   = (const float*)d_in[1];
    const float* values = (const float*)d_in[2];
    const float* usage  = (const float*)d_in[3];
    // d_in[4] = k (fixed to 8 by problem shape / out_size)

    float* out       = (float*)d_out;
    float* out_keys  = out;
    float* out_vals  = out + (size_t)BQ * KSEL * DIM;
    float* out_usage = out + (size_t)2 * BQ * KSEL * DIM;

    cudaFuncSetAttribute(gemm_kernel, cudaFuncAttributeMaxDynamicSharedMemorySize, SMEM_DYN);

    prep_q_kernel<<<(BQ * DIM / 4) / 256, 256>>>((const float4*)query);
    prep_keys_kernel<<<CC, 256>>>(keys);

    dim3 ggrid(CC / BN, BQ / BM);       // (512, 16)
    gemm_kernel<<<ggrid, 256, SMEM_DYN>>>();

    select_kernel<<<BQ, 256>>>();
    usage_init_kernel<<<CC / 256, 256>>>(usage, out_usage);
    rescore_gather_kernel<<<BQ, 256>>>(query, keys, values, out_keys, out_vals, out_usage);
}